// round 15
// baseline (speedup 1.0000x reference)
#include <cuda_runtime.h>
#include <cuda_bf16.h>

// AggregationLoss on GB300 (sm_103a) — single fused pipelined kernel.
// Ticket scheduler: order p1(b0), p1(b1), p2(b0), p1(b2), p2(b1), ... so
// pass1 (ATOMS/L1tex-bound, DRAM 41%) and pass2 (DRAM-bound, L1tex 34%)
// overlap on complementary resources, and pass2(b) reads batch b's data
// while it is still L2-resident from pass1(b).
// pass1 tile: 3 smem ATOMS / 10 B per px (psum bf16x2 pairs + joint km table
//   whose row/col sums give ksum/rsum), packed-label STG; flush -> g_tab,
//   release via __threadfence + per-batch counter.
// pass2 tile: spin-acquire on its batch counter, LUT from g_tab (__ldcg),
//   per-pixel loss, block reduce -> double accumulator. Last p2 block writes
//   the scalar and resets all scratch in parallel (next graph replay).
//
// Shapes fixed: B=16, C=4, N = 736*736 = 541696 (T = 529 tiles, no tail).

#define BATCH 16
#define CHAN 4
#define NSEG 33
#define NQ 6          // g_tab: q0=ksum, q1..q4=psum[c], q5=rsum
#define NREP 4
#define JREP 2
#define THREADS 256
#define PXPT 4
#define NPX_CAP (16 * 736 * 736)   // 8,667,136

// ---- device scratch (allocation-free; zero at module load) ----
__device__ float  g_tab[BATCH][NQ][NSEG];
__device__ int    g_kmax;
__device__ double g_acc;
__device__ unsigned int g_ticket;
__device__ unsigned int g_cnt[BATCH];      // pass1 completion per batch
__device__ unsigned int g_done;            // pass2 completion
__device__ unsigned short g_lab[NPX_CAP];  // klab | (rlab<<8)

__global__ void __launch_bounds__(THREADS) fused_kernel(
    const float* __restrict__ pred,   // [B, C, N]
    const float* __restrict__ rmask,  // [B, N]
    const float* __restrict__ kmask,  // [B, N]
    const int*   __restrict__ klab,   // [B, N]
    const int*   __restrict__ rlab,   // [B, N]
    float* __restrict__ out,
    int N, int T)
{
    __shared__ __nv_bfloat162 s_pA[NREP * NSEG];        // (q0, q1)
    __shared__ __nv_bfloat162 s_pB[NREP * NSEG];        // (q2, q3)
    __shared__ __nv_bfloat16  s_j[JREP * NSEG * NSEG];  // km joint table
    __shared__ float s_gc[CHAN][NSEG];
    __shared__ float s_rinv[NSEG];
    __shared__ float s_part[THREADS / 32];
    __shared__ unsigned int s_tk;
    __shared__ int s_last;

    const int t = threadIdx.x;
    if (t == 0) s_tk = atomicAdd(&g_ticket, 1u);
    __syncthreads();
    const unsigned tk = s_tk;
    const unsigned uT = (unsigned)T;

    // ticket -> (pass, batch, tile): p1(b0) | {p1(bk+1), p2(bk)}k=0..14 | p2(b15)
    int pass, b, tile;
    if (tk < uT) {
        pass = 1; b = 0; tile = (int)tk;
    } else if (tk < 31u * uT) {
        const unsigned u = tk - uT;
        const int k = (int)(u / (2u * uT));
        const unsigned w = u - (unsigned)k * 2u * uT;
        if (w < uT) { pass = 1; b = k + 1; tile = (int)w; }
        else        { pass = 2; b = k;     tile = (int)(w - uT); }
    } else {
        pass = 2; b = BATCH - 1; tile = (int)(tk - 31u * uT);
    }

    const size_t base = (size_t)b * N;
    const int n0 = (tile * THREADS + t) * PXPT;

    if (pass == 1) {
        // ---------------- pass 1 ----------------
        const int r = t & (NREP - 1);
        const int jr = (t & 1) * (NSEG * NSEG);

        for (int i = t; i < NREP * NSEG; i += THREADS) {
            *(unsigned int*)&s_pA[i] = 0u;
            *(unsigned int*)&s_pB[i] = 0u;
        }
        for (int i = t; i < JREP * NSEG * NSEG; i += THREADS)
            *(unsigned short*)&s_j[i] = 0;
        __syncthreads();

        int local_kmax = 0;

        if (n0 + PXPT <= N) {
            int4   kl4 = *(const int4*)(klab + base + n0);
            int4   rl4 = *(const int4*)(rlab + base + n0);
            float4 km4 = *(const float4*)(kmask + base + n0);
            float4 pv[CHAN];
            const float* pb = pred + (size_t)b * CHAN * N + n0;
#pragma unroll
            for (int c = 0; c < CHAN; c++) pv[c] = *(const float4*)(pb + (size_t)c * N);

            int kls[4] = { kl4.x, kl4.y, kl4.z, kl4.w };
            int rls[4] = { rl4.x, rl4.y, rl4.z, rl4.w };
            float kms[4] = { km4.x, km4.y, km4.z, km4.w };
            float prs[CHAN][4];
#pragma unroll
            for (int c = 0; c < CHAN; c++) {
                prs[c][0] = pv[c].x; prs[c][1] = pv[c].y;
                prs[c][2] = pv[c].z; prs[c][3] = pv[c].w;
            }

            *(uint2*)&g_lab[base + n0] = make_uint2(
                (unsigned int)(kls[0] | (rls[0] << 8))
                    | ((unsigned int)(kls[1] | (rls[1] << 8)) << 16),
                (unsigned int)(kls[2] | (rls[2] << 8))
                    | ((unsigned int)(kls[3] | (rls[3] << 8)) << 16));

#pragma unroll
            for (int j = 0; j < 4; j++) {
                const int kl = kls[j], rl = rls[j];
                const int idx = r * NSEG + kl;
                local_kmax = max(local_kmax, kl);
                atomicAdd(&s_pA[idx], __floats2bfloat162_rn(prs[0][j], prs[1][j]));
                atomicAdd(&s_pB[idx], __floats2bfloat162_rn(prs[2][j], prs[3][j]));
                atomicAdd(&s_j[jr + kl * NSEG + rl], __float2bfloat16_rn(kms[j]));
            }
        } else if (n0 < N) {
            const float* pb = pred + (size_t)b * CHAN * N;
            for (int j = 0; j < PXPT; j++) {
                const int n = n0 + j;
                if (n >= N) break;
                const int kl = klab[base + n], rl = rlab[base + n];
                const float km = kmask[base + n];
                const int idx = r * NSEG + kl;
                local_kmax = max(local_kmax, kl);
                atomicAdd(&s_pA[idx], __floats2bfloat162_rn(pb[0 * (size_t)N + n],
                                                            pb[1 * (size_t)N + n]));
                atomicAdd(&s_pB[idx], __floats2bfloat162_rn(pb[2 * (size_t)N + n],
                                                            pb[3 * (size_t)N + n]));
                atomicAdd(&s_j[jr + kl * NSEG + rl], __float2bfloat16_rn(km));
                g_lab[base + n] = (unsigned short)(kl | (rl << 8));
            }
        }
        __syncthreads();

        // flush to g_tab
        for (int i = t; i < NSEG; i += THREADS) {
            float v0 = 0.f, v1 = 0.f, v2 = 0.f, v3 = 0.f;
#pragma unroll
            for (int rr = 0; rr < NREP; rr++) {
                float2 fA = __bfloat1622float2(s_pA[rr * NSEG + i]);
                float2 fB = __bfloat1622float2(s_pB[rr * NSEG + i]);
                v0 += fA.x; v1 += fA.y; v2 += fB.x; v3 += fB.y;
            }
            float ks = 0.f, rs = 0.f;
            for (int o = 0; o < NSEG; o++) {
#pragma unroll
                for (int rep = 0; rep < JREP; rep++) {
                    ks += __bfloat162float(s_j[rep * NSEG * NSEG + i * NSEG + o]);
                    rs += __bfloat162float(s_j[rep * NSEG * NSEG + o * NSEG + i]);
                }
            }
            if (ks != 0.f) atomicAdd(&g_tab[b][0][i], ks);
            if (v0 != 0.f) atomicAdd(&g_tab[b][1][i], v0);
            if (v1 != 0.f) atomicAdd(&g_tab[b][2][i], v1);
            if (v2 != 0.f) atomicAdd(&g_tab[b][3][i], v2);
            if (v3 != 0.f) atomicAdd(&g_tab[b][4][i], v3);
            if (rs != 0.f) atomicAdd(&g_tab[b][5][i], rs);
        }

        if (b == BATCH - 1) {
#pragma unroll
            for (int o = 16; o; o >>= 1)
                local_kmax = max(local_kmax, __shfl_xor_sync(0xffffffffu, local_kmax, o));
            if ((t & 31) == 0) atomicMax(&g_kmax, local_kmax);
        }

        // release: every thread fences its own writes, then tid0 signals
        __threadfence();
        __syncthreads();
        if (t == 0) atomicAdd(&g_cnt[b], 1u);

    } else {
        // ---------------- pass 2 ----------------
        if (t == 0) {
            while (*(volatile unsigned int*)&g_cnt[b] < (unsigned)T) __nanosleep(64);
            __threadfence();   // acquire
        }
        __syncthreads();

        if (t < NSEG) {
            const float ksv = __ldcg(&g_tab[b][0][t]);
            const float rsv = __ldcg(&g_tab[b][5][t]);
            const float invk = (t == 0) ? 0.f : 1.f / (ksv + 1.f);
#pragma unroll
            for (int c = 0; c < CHAN; c++)
                s_gc[c][t] = __ldcg(&g_tab[b][1 + c][t]) * invk;
            s_rinv[t] = (t == 0) ? 1.f : 1.f / (rsv + 1.f);
        }
        __syncthreads();

        float acc = 0.f;
        if (n0 + PXPT <= N) {
            uint2  lab = __ldcg((const uint2*)&g_lab[base + n0]);
            float4 rm4 = *(const float4*)(rmask + base + n0);
            float4 pv[CHAN];
            const float* pb = pred + (size_t)b * CHAN * N + n0;
#pragma unroll
            for (int c = 0; c < CHAN; c++) pv[c] = *(const float4*)(pb + (size_t)c * N);

            unsigned short ws[4] = {
                (unsigned short)(lab.x & 0xffff), (unsigned short)(lab.x >> 16),
                (unsigned short)(lab.y & 0xffff), (unsigned short)(lab.y >> 16) };
            float rms[4] = { rm4.x, rm4.y, rm4.z, rm4.w };
            float prs[CHAN][4];
#pragma unroll
            for (int c = 0; c < CHAN; c++) {
                prs[c][0] = pv[c].x; prs[c][1] = pv[c].y;
                prs[c][2] = pv[c].z; prs[c][3] = pv[c].w;
            }
#pragma unroll
            for (int j = 0; j < 4; j++) {
                const int kl = ws[j] & 0xff;
                const int rl = ws[j] >> 8;
                const float rm = rms[j];
                float n2 = 0.f;
#pragma unroll
                for (int c = 0; c < CHAN; c++) {
                    float d = fmaf(prs[c][j], rm, -s_gc[c][kl]);
                    n2 = fmaf(d, d, n2);
                }
                float nr = sqrtf(n2);
                float dd = fmaxf(nr - 0.5f, 0.f);
                acc += __logf(fmaf(dd, dd, 1.f)) * s_rinv[rl];
            }
        } else if (n0 < N) {
            const float* pb = pred + (size_t)b * CHAN * N;
            for (int j = 0; j < PXPT; j++) {
                const int n = n0 + j;
                if (n >= N) break;
                const unsigned short w =
                    (unsigned short)__ldcg((const unsigned short*)&g_lab[base + n]);
                const int kl = w & 0xff;
                const int rl = w >> 8;
                const float rm = rmask[base + n];
                float n2 = 0.f;
                for (int c = 0; c < CHAN; c++) {
                    float d = fmaf(pb[(size_t)c * N + n], rm, -s_gc[c][kl]);
                    n2 = fmaf(d, d, n2);
                }
                float nr = sqrtf(n2);
                float dd = fmaxf(nr - 0.5f, 0.f);
                acc += __logf(fmaf(dd, dd, 1.f)) * s_rinv[rl];
            }
        }

#pragma unroll
        for (int o = 16; o; o >>= 1) acc += __shfl_xor_sync(0xffffffffu, acc, o);
        if ((t & 31) == 0) s_part[t >> 5] = acc;
        __syncthreads();

        if (t == 0) {
            float s = 0.f;
#pragma unroll
            for (int i = 0; i < THREADS / 32; i++) s += s_part[i];
            atomicAdd(&g_acc, (double)s);
            __threadfence();
            const unsigned int total = (unsigned)(BATCH * T);
            s_last = (atomicAdd(&g_done, 1u) == total - 1u) ? 1 : 0;
        }
        __syncthreads();

        if (s_last) {
            if (t == 0) {
                __threadfence();
                const double a = atomicAdd(&g_acc, 0.0);
                const int km = atomicMax(&g_kmax, 0);
                out[0] = (float)(a / (double)km);
            }
            float* tp = &g_tab[0][0][0];
            for (int i = t; i < BATCH * NQ * NSEG; i += THREADS) tp[i] = 0.f;
            if (t < BATCH) g_cnt[t] = 0u;
            __syncthreads();
            if (t == 0) {
                g_acc = 0.0;
                g_kmax = 0;
                g_ticket = 0u;
                __threadfence();
                g_done = 0u;
            }
        }
    }
}

extern "C" void kernel_launch(void* const* d_in, const int* in_sizes, int n_in,
                              void* d_out, int out_size) {
    const float* pred  = (const float*)d_in[0];
    const float* rmask = (const float*)d_in[1];
    const float* kmask = (const float*)d_in[2];
    const int*   rlab  = (const int*)d_in[3];
    const int*   klab  = (const int*)d_in[4];

    const int N = in_sizes[1] / BATCH;
    const int T = (N + THREADS * PXPT - 1) / (THREADS * PXPT);  // 529

    fused_kernel<<<2 * BATCH * T, THREADS>>>(pred, rmask, kmask, klab, rlab,
                                             (float*)d_out, N, T);
}

// round 16
// speedup vs baseline: 1.4691x; 1.4691x over previous
#include <cuda_runtime.h>
#include <cuda_bf16.h>

// AggregationLoss on GB300 (sm_103a).
// pass1: per-batch segment sums over 33 labels with 3 smem ATOMS / 10 B per px
//        (psum bf16x2 pairs by klab + joint bf16 T[kl][rl]+=km whose row/col
//        sums give ksum/rsum). Packed-label STG for pass2. ITERS=2 tiles per
//        block (halves init/flush overhead) and a PARALLEL joint-table flush
//        (264 workers + shfl instead of 33 serial threads).
// pass2: DRAM-bound loss pass reading pred + rmask (fp32) + packed labels
//        (R12 form, untouched).
// finalize: writes scalar, zeroes g_tab for the next graph replay (R12 form).
//
// Shapes fixed: B=16, C=4, N = 736*736 = 541696 (529 tiles of 1024 px).

#define BATCH 16
#define CHAN 4
#define NSEG 33
#define NQ 6          // g_tab: q0=ksum, q1..q4=psum[c], q5=rsum
#define NREP 4        // replicas for psum pair tables
#define JREP 2        // replicas for joint (kl,rl) table
#define THREADS 256
#define PXPT 4
#define ITERS 2       // tiles per pass1 block
#define NPX_CAP (16 * 736 * 736)   // 8,667,136

// ---- device scratch (allocation-free; zero at module load) ----
__device__ float  g_tab[BATCH][NQ][NSEG];
__device__ int    g_kmax;
__device__ double g_acc;
__device__ unsigned short g_lab[NPX_CAP];  // klab | (rlab<<8)

__global__ void __launch_bounds__(THREADS) pass1_kernel(
    const float* __restrict__ pred,   // [B, C, N]
    const float* __restrict__ kmask,  // [B, N]
    const int*   __restrict__ klab,   // [B, N]
    const int*   __restrict__ rlab,   // [B, N]
    int N)
{
    __shared__ __nv_bfloat162 s_pA[NREP * NSEG];        // (q0, q1)
    __shared__ __nv_bfloat162 s_pB[NREP * NSEG];        // (q2, q3)
    __shared__ __nv_bfloat16  s_j[JREP * NSEG * NSEG];  // km joint table
    __shared__ float s_ks[NSEG];
    __shared__ float s_rs[NSEG];

    const int t = threadIdx.x;
    const int b = blockIdx.y;
    const int r = t & (NREP - 1);
    const int jr = (t & 1) * (NSEG * NSEG);

    for (int i = t; i < NREP * NSEG; i += THREADS) {
        *(unsigned int*)&s_pA[i] = 0u;
        *(unsigned int*)&s_pB[i] = 0u;
    }
    for (int i = t; i < JREP * NSEG * NSEG; i += THREADS)
        *(unsigned short*)&s_j[i] = 0;
    __syncthreads();

    const size_t base = (size_t)b * N;
    int local_kmax = 0;

#pragma unroll
    for (int it = 0; it < ITERS; it++) {
        const int n0 = ((blockIdx.x * ITERS + it) * THREADS + t) * PXPT;

        if (n0 + PXPT <= N) {
            int4   kl4 = *(const int4*)(klab + base + n0);
            int4   rl4 = *(const int4*)(rlab + base + n0);
            float4 km4 = *(const float4*)(kmask + base + n0);
            float4 pv[CHAN];
            const float* pb = pred + (size_t)b * CHAN * N + n0;
#pragma unroll
            for (int c = 0; c < CHAN; c++) pv[c] = *(const float4*)(pb + (size_t)c * N);

            int kls[4] = { kl4.x, kl4.y, kl4.z, kl4.w };
            int rls[4] = { rl4.x, rl4.y, rl4.z, rl4.w };
            float kms[4] = { km4.x, km4.y, km4.z, km4.w };
            float prs[CHAN][4];
#pragma unroll
            for (int c = 0; c < CHAN; c++) {
                prs[c][0] = pv[c].x; prs[c][1] = pv[c].y;
                prs[c][2] = pv[c].z; prs[c][3] = pv[c].w;
            }

            // packed labels: one STG.64 per 4 px
            *(uint2*)&g_lab[base + n0] = make_uint2(
                (unsigned int)(kls[0] | (rls[0] << 8))
                    | ((unsigned int)(kls[1] | (rls[1] << 8)) << 16),
                (unsigned int)(kls[2] | (rls[2] << 8))
                    | ((unsigned int)(kls[3] | (rls[3] << 8)) << 16));

            // 3 smem atomics / 10 B per px
#pragma unroll
            for (int j = 0; j < 4; j++) {
                const int kl = kls[j], rl = rls[j];
                const int idx = r * NSEG + kl;
                local_kmax = max(local_kmax, kl);
                atomicAdd(&s_pA[idx], __floats2bfloat162_rn(prs[0][j], prs[1][j]));
                atomicAdd(&s_pB[idx], __floats2bfloat162_rn(prs[2][j], prs[3][j]));
                atomicAdd(&s_j[jr + kl * NSEG + rl], __float2bfloat16_rn(kms[j]));
            }
        } else if (n0 < N) {
            const float* pb = pred + (size_t)b * CHAN * N;
            for (int j = 0; j < PXPT; j++) {
                const int n = n0 + j;
                if (n >= N) break;
                const int kl = klab[base + n], rl = rlab[base + n];
                const float km = kmask[base + n];
                const int idx = r * NSEG + kl;
                local_kmax = max(local_kmax, kl);
                atomicAdd(&s_pA[idx], __floats2bfloat162_rn(pb[0 * (size_t)N + n],
                                                            pb[1 * (size_t)N + n]));
                atomicAdd(&s_pB[idx], __floats2bfloat162_rn(pb[2 * (size_t)N + n],
                                                            pb[3 * (size_t)N + n]));
                atomicAdd(&s_j[jr + kl * NSEG + rl], __float2bfloat16_rn(km));
                g_lab[base + n] = (unsigned short)(kl | (rl << 8));
            }
        }
    }
    __syncthreads();

    // ---- parallel joint-table flush: ksum (row sums) / rsum (col sums) ----
    {
        // labels 0..31: all 256 threads, 8 workers per label
        const int i = t >> 3, part = t & 7;
        float ks = 0.f, rs = 0.f;
        for (int o = part; o < NSEG; o += 8) {
            ks += __bfloat162float(s_j[i * NSEG + o])
                + __bfloat162float(s_j[NSEG * NSEG + i * NSEG + o]);
            rs += __bfloat162float(s_j[o * NSEG + i])
                + __bfloat162float(s_j[NSEG * NSEG + o * NSEG + i]);
        }
        ks += __shfl_down_sync(0xffffffffu, ks, 4, 8);
        ks += __shfl_down_sync(0xffffffffu, ks, 2, 8);
        ks += __shfl_down_sync(0xffffffffu, ks, 1, 8);
        rs += __shfl_down_sync(0xffffffffu, rs, 4, 8);
        rs += __shfl_down_sync(0xffffffffu, rs, 2, 8);
        rs += __shfl_down_sync(0xffffffffu, rs, 1, 8);
        if (part == 0) { s_ks[i] = ks; s_rs[i] = rs; }
    }
    if (t < 8) {
        // label 32: lanes 0..7 of warp 0
        const int i = 32, part = t;
        float ks = 0.f, rs = 0.f;
        for (int o = part; o < NSEG; o += 8) {
            ks += __bfloat162float(s_j[i * NSEG + o])
                + __bfloat162float(s_j[NSEG * NSEG + i * NSEG + o]);
            rs += __bfloat162float(s_j[o * NSEG + i])
                + __bfloat162float(s_j[NSEG * NSEG + o * NSEG + i]);
        }
        ks += __shfl_down_sync(0xffu, ks, 4, 8);
        ks += __shfl_down_sync(0xffu, ks, 2, 8);
        ks += __shfl_down_sync(0xffu, ks, 1, 8);
        rs += __shfl_down_sync(0xffu, rs, 4, 8);
        rs += __shfl_down_sync(0xffu, rs, 2, 8);
        rs += __shfl_down_sync(0xffu, rs, 1, 8);
        if (part == 0) { s_ks[32] = ks; s_rs[32] = rs; }
    }
    __syncthreads();

    // global flush: psum from replicas + staged ksum/rsum
    for (int i = t; i < NSEG; i += THREADS) {
        float v0 = 0.f, v1 = 0.f, v2 = 0.f, v3 = 0.f;
#pragma unroll
        for (int rr = 0; rr < NREP; rr++) {
            float2 fA = __bfloat1622float2(s_pA[rr * NSEG + i]);
            float2 fB = __bfloat1622float2(s_pB[rr * NSEG + i]);
            v0 += fA.x; v1 += fA.y; v2 += fB.x; v3 += fB.y;
        }
        const float ks = s_ks[i], rs = s_rs[i];
        if (ks != 0.f) atomicAdd(&g_tab[b][0][i], ks);
        if (v0 != 0.f) atomicAdd(&g_tab[b][1][i], v0);
        if (v1 != 0.f) atomicAdd(&g_tab[b][2][i], v1);
        if (v2 != 0.f) atomicAdd(&g_tab[b][3][i], v2);
        if (v3 != 0.f) atomicAdd(&g_tab[b][4][i], v3);
        if (rs != 0.f) atomicAdd(&g_tab[b][5][i], rs);
    }

    if (b == BATCH - 1) {
#pragma unroll
        for (int o = 16; o; o >>= 1)
            local_kmax = max(local_kmax, __shfl_xor_sync(0xffffffffu, local_kmax, o));
        if ((t & 31) == 0) atomicMax(&g_kmax, local_kmax);
    }
}

__global__ void __launch_bounds__(THREADS) pass2_kernel(
    const float* __restrict__ pred,   // [B, C, N]
    const float* __restrict__ rmask,  // [B, N]
    int N)
{
    __shared__ float s_gc[CHAN][NSEG];
    __shared__ float s_rinv[NSEG];
    __shared__ float s_part[THREADS / 32];

    const int t = threadIdx.x;
    const int b = blockIdx.y;

    if (t < NSEG) {
        const float invk = (t == 0) ? 0.f : 1.f / (g_tab[b][0][t] + 1.f);
#pragma unroll
        for (int c = 0; c < CHAN; c++) s_gc[c][t] = g_tab[b][1 + c][t] * invk;
        s_rinv[t] = (t == 0) ? 1.f : 1.f / (g_tab[b][5][t] + 1.f);
    }
    __syncthreads();

    float acc = 0.f;
    const int n0 = (blockIdx.x * THREADS + t) * PXPT;
    const size_t base = (size_t)b * N;

    if (n0 + PXPT <= N) {
        uint2  lab = *(const uint2*)&g_lab[base + n0];
        float4 rm4 = *(const float4*)(rmask + base + n0);
        float4 pv[CHAN];
        const float* pb = pred + (size_t)b * CHAN * N + n0;
#pragma unroll
        for (int c = 0; c < CHAN; c++) pv[c] = *(const float4*)(pb + (size_t)c * N);

        unsigned short ws[4] = {
            (unsigned short)(lab.x & 0xffff), (unsigned short)(lab.x >> 16),
            (unsigned short)(lab.y & 0xffff), (unsigned short)(lab.y >> 16) };
        float rms[4] = { rm4.x, rm4.y, rm4.z, rm4.w };
        float prs[CHAN][4];
#pragma unroll
        for (int c = 0; c < CHAN; c++) {
            prs[c][0] = pv[c].x; prs[c][1] = pv[c].y;
            prs[c][2] = pv[c].z; prs[c][3] = pv[c].w;
        }
#pragma unroll
        for (int j = 0; j < 4; j++) {
            const int kl = ws[j] & 0xff;
            const int rl = ws[j] >> 8;
            const float rm = rms[j];
            float n2 = 0.f;
#pragma unroll
            for (int c = 0; c < CHAN; c++) {
                float d = fmaf(prs[c][j], rm, -s_gc[c][kl]);
                n2 = fmaf(d, d, n2);
            }
            float nr = sqrtf(n2);
            float dd = fmaxf(nr - 0.5f, 0.f);
            acc += __logf(fmaf(dd, dd, 1.f)) * s_rinv[rl];
        }
    } else if (n0 < N) {
        const float* pb = pred + (size_t)b * CHAN * N;
        for (int j = 0; j < PXPT; j++) {
            const int n = n0 + j;
            if (n >= N) break;
            const unsigned short w = g_lab[base + n];
            const int kl = w & 0xff;
            const int rl = w >> 8;
            const float rm = rmask[base + n];
            float n2 = 0.f;
            for (int c = 0; c < CHAN; c++) {
                float d = fmaf(pb[(size_t)c * N + n], rm, -s_gc[c][kl]);
                n2 = fmaf(d, d, n2);
            }
            float nr = sqrtf(n2);
            float dd = fmaxf(nr - 0.5f, 0.f);
            acc += __logf(fmaf(dd, dd, 1.f)) * s_rinv[rl];
        }
    }

#pragma unroll
    for (int o = 16; o; o >>= 1) acc += __shfl_xor_sync(0xffffffffu, acc, o);
    if ((t & 31) == 0) s_part[t >> 5] = acc;
    __syncthreads();
    if (t == 0) {
        float s = 0.f;
#pragma unroll
        for (int i = 0; i < THREADS / 32; i++) s += s_part[i];
        atomicAdd(&g_acc, (double)s);
    }
}

__global__ void finalize_kernel(float* __restrict__ out) {
    const int t = threadIdx.x;
    if (t == 0) out[0] = (float)(g_acc / (double)g_kmax);
    __syncthreads();
    float* tp = &g_tab[0][0][0];
    for (int i = t; i < BATCH * NQ * NSEG; i += blockDim.x) tp[i] = 0.f;
    if (t == 0) { g_kmax = 0; g_acc = 0.0; }
}

extern "C" void kernel_launch(void* const* d_in, const int* in_sizes, int n_in,
                              void* d_out, int out_size) {
    const float* pred  = (const float*)d_in[0];
    const float* rmask = (const float*)d_in[1];
    const float* kmask = (const float*)d_in[2];
    const int*   rlab  = (const int*)d_in[3];
    const int*   klab  = (const int*)d_in[4];

    const int N = in_sizes[1] / BATCH;
    const int blocks1 = (N + THREADS * PXPT * ITERS - 1) / (THREADS * PXPT * ITERS);
    const int blocks2 = (N + THREADS * PXPT - 1) / (THREADS * PXPT);
    dim3 grid1(blocks1, BATCH);
    dim3 grid2(blocks2, BATCH);

    pass1_kernel<<<grid1, THREADS>>>(pred, kmask, klab, rlab, N);
    pass2_kernel<<<grid2, THREADS>>>(pred, rmask, N);
    finalize_kernel<<<1, 256>>>((float*)d_out);
}